// round 7
// baseline (speedup 1.0000x reference)
#include <cuda_runtime.h>
#include <cuda_fp16.h>
#include <math.h>

#define NNODES 100000
#define EDGES  3200000
#define HDIM   128
#define EDIM   16
#define PTYPES 6

// ---- __device__ scratch (allocations are banned) ----
// g_cnt invariant: zero at kernel_launch entry (zero-initialized at load;
// k_scan re-zeroes it after consuming, every replay).
__device__ int    g_cnt[NNODES];
__device__ int    g_rowptr[NNODES + 1];
__device__ int    g_rowpos[NNODES];
__device__ int    g_col_s[EDGES];       // CSR-ordered packed (col | ptype<<24)
__device__ __half g_kh[NNODES * HDIM];  // fp16 k     (25.6 MB)
__device__ __half g_vh[NNODES * HDIM];  // fp16 v     (25.6 MB)
__device__ __half g_eh[NNODES * EDIM];  // fp16 eigs   (3.2 MB)
__device__ float  g_pexp[PTYPES];
__device__ float  g_expl;

// ---------------------------------------------------------------------------
// 0) prep + hist in one kernel (independent work; g_cnt already zero)
// ---------------------------------------------------------------------------
__global__ void k_prep_hist(const float* __restrict__ k,
                            const float* __restrict__ v,
                            const float* __restrict__ eigs,
                            const float* __restrict__ lambda0,
                            const float* __restrict__ path_w,
                            const int* __restrict__ indices,
                            int n_nodes, int n_edges) {
    int tid = blockIdx.x * blockDim.x + threadIdx.x;
    int stride = gridDim.x * blockDim.x;

    int nk4 = n_nodes * (HDIM / 4);
    for (int i = tid; i < nk4; i += stride) {
        float4 f = __ldg(reinterpret_cast<const float4*>(k) + i);
        __half2 lo = __floats2half2_rn(f.x, f.y);
        __half2 hi = __floats2half2_rn(f.z, f.w);
        uint2 o;
        o.x = *reinterpret_cast<unsigned*>(&lo);
        o.y = *reinterpret_cast<unsigned*>(&hi);
        reinterpret_cast<uint2*>(g_kh)[i] = o;
    }
    for (int i = tid; i < nk4; i += stride) {
        float4 f = __ldg(reinterpret_cast<const float4*>(v) + i);
        __half2 lo = __floats2half2_rn(f.x, f.y);
        __half2 hi = __floats2half2_rn(f.z, f.w);
        uint2 o;
        o.x = *reinterpret_cast<unsigned*>(&lo);
        o.y = *reinterpret_cast<unsigned*>(&hi);
        reinterpret_cast<uint2*>(g_vh)[i] = o;
    }
    int ne4 = n_nodes * (EDIM / 4);
    for (int i = tid; i < ne4; i += stride) {
        float4 f = __ldg(reinterpret_cast<const float4*>(eigs) + i);
        __half2 lo = __floats2half2_rn(f.x, f.y);
        __half2 hi = __floats2half2_rn(f.z, f.w);
        uint2 o;
        o.x = *reinterpret_cast<unsigned*>(&lo);
        o.y = *reinterpret_cast<unsigned*>(&hi);
        reinterpret_cast<uint2*>(g_eh)[i] = o;
    }

    // histogram (8 edges per iter, vectorized)
    int ne8 = n_edges / 8;
    for (int t = tid; t < ne8; t += stride) {
        int4 a = __ldg(reinterpret_cast<const int4*>(indices) + t * 2);
        int4 b = __ldg(reinterpret_cast<const int4*>(indices) + t * 2 + 1);
        atomicAdd(&g_cnt[a.x], 1); atomicAdd(&g_cnt[a.y], 1);
        atomicAdd(&g_cnt[a.z], 1); atomicAdd(&g_cnt[a.w], 1);
        atomicAdd(&g_cnt[b.x], 1); atomicAdd(&g_cnt[b.y], 1);
        atomicAdd(&g_cnt[b.z], 1); atomicAdd(&g_cnt[b.w], 1);
    }
    for (int e = ne8 * 8 + tid; e < n_edges; e += stride)
        atomicAdd(&g_cnt[__ldg(indices + e)], 1);

    if (tid < PTYPES) g_pexp[tid] = expf(path_w[tid]);
    if (tid == 0)     g_expl = expf(lambda0[0]);
}

// ---------------------------------------------------------------------------
// 1) exclusive scan (single block); re-zeroes g_cnt for the next replay
// ---------------------------------------------------------------------------
__global__ void k_scan(int n) {
    __shared__ int part[1024];
    int tid = threadIdx.x;
    int chunk = (n + 1023) / 1024;
    int start = tid * chunk;
    int end   = min(start + chunk, n);
    int s = 0;
    for (int i = start; i < end; i++) s += g_cnt[i];
    part[tid] = s;
    __syncthreads();
    for (int off = 1; off < 1024; off <<= 1) {
        int v = 0;
        if (tid >= off) v = part[tid - off];
        __syncthreads();
        if (tid >= off) part[tid] += v;
        __syncthreads();
    }
    int run = (tid == 0) ? 0 : part[tid - 1];
    for (int i = start; i < end; i++) {
        int c = g_cnt[i];
        g_cnt[i] = 0;              // restore invariant for next replay
        g_rowptr[i] = run;
        g_rowpos[i] = run;
        run += c;
    }
    if (end == n && start <= n) g_rowptr[n] = run;
}

// ---------------------------------------------------------------------------
// 2) scatter — 8 edges/thread, single packed 4B write per edge
// ---------------------------------------------------------------------------
__global__ void k_scatter(const int* __restrict__ indices,
                          const int* __restrict__ ptype, int n_edges) {
    int t = blockIdx.x * blockDim.x + threadIdx.x;
    int base = t * 8;
    if (base + 8 <= n_edges) {
        int4 r0 = __ldg(reinterpret_cast<const int4*>(indices) + t * 2);
        int4 r1 = __ldg(reinterpret_cast<const int4*>(indices) + t * 2 + 1);
        int4 c0 = __ldg(reinterpret_cast<const int4*>(indices + n_edges) + t * 2);
        int4 c1 = __ldg(reinterpret_cast<const int4*>(indices + n_edges) + t * 2 + 1);
        int4 p0 = __ldg(reinterpret_cast<const int4*>(ptype) + t * 2);
        int4 p1 = __ldg(reinterpret_cast<const int4*>(ptype) + t * 2 + 1);
        int pos;
        pos = atomicAdd(&g_rowpos[r0.x], 1); g_col_s[pos] = c0.x | (p0.x << 24);
        pos = atomicAdd(&g_rowpos[r0.y], 1); g_col_s[pos] = c0.y | (p0.y << 24);
        pos = atomicAdd(&g_rowpos[r0.z], 1); g_col_s[pos] = c0.z | (p0.z << 24);
        pos = atomicAdd(&g_rowpos[r0.w], 1); g_col_s[pos] = c0.w | (p0.w << 24);
        pos = atomicAdd(&g_rowpos[r1.x], 1); g_col_s[pos] = c1.x | (p1.x << 24);
        pos = atomicAdd(&g_rowpos[r1.y], 1); g_col_s[pos] = c1.y | (p1.y << 24);
        pos = atomicAdd(&g_rowpos[r1.z], 1); g_col_s[pos] = c1.z | (p1.z << 24);
        pos = atomicAdd(&g_rowpos[r1.w], 1); g_col_s[pos] = c1.w | (p1.w << 24);
    } else {
        for (int e = base; e < n_edges; e++) {
            int row = __ldg(indices + e);
            int col = __ldg(indices + n_edges + e);
            int pt  = __ldg(ptype + e);
            int pos = atomicAdd(&g_rowpos[row], 1);
            g_col_s[pos] = col | (pt << 24);
        }
    }
}

// ---------------------------------------------------------------------------
// 3) fused pass: warp per row, HALF-WARP per edge.
//    lanes 0-15 -> even edge, lanes 16-31 -> odd edge. Each lane covers 8
//    head components via uint4 fp16 loads; score reduced with 4 shfl steps.
// ---------------------------------------------------------------------------
__device__ __forceinline__ float dot8h(float4 qa, float4 qb, uint4 kr) {
    float2 k0 = __half22float2(*reinterpret_cast<__half2*>(&kr.x));
    float2 k1 = __half22float2(*reinterpret_cast<__half2*>(&kr.y));
    float2 k2 = __half22float2(*reinterpret_cast<__half2*>(&kr.z));
    float2 k3 = __half22float2(*reinterpret_cast<__half2*>(&kr.w));
    return qa.x * k0.x + qa.y * k0.y + qa.z * k1.x + qa.w * k1.y
         + qb.x * k2.x + qb.y * k2.y + qb.z * k3.x + qb.w * k3.y;
}

__global__ void __launch_bounds__(256)
k_fused(const float* __restrict__ q, float* __restrict__ out, int n_nodes) {
    __shared__ float s_pexp[PTYPES];
    if (threadIdx.x < PTYPES) s_pexp[threadIdx.x] = g_pexp[threadIdx.x];
    __syncthreads();

    int warp = (blockIdx.x * blockDim.x + threadIdx.x) >> 5;
    int lane = threadIdx.x & 31;
    if (warp >= n_nodes) return;
    const int row  = warp;
    const int half = lane >> 4;   // which edge of the pair
    const int hl   = lane & 15;   // lane within half: components 8hl..8hl+7
    const int beg = g_rowptr[row];
    const int end = g_rowptr[row + 1];

    float acc0[8] = {0,0,0,0,0,0,0,0};
    float acc1[8] = {0,0,0,0,0,0,0,0};
    float d0 = 0.f, d1 = 0.f;
    float res[8];

    if (beg < end) {
        const float inv_sqrt_h = 0.08838834764831845f;  // 1/sqrt(128)
        const float* qrow = q + (size_t)row * HDIM + hl * 8;
        float4 qa = __ldg(reinterpret_cast<const float4*>(qrow));
        float4 qb = __ldg(reinterpret_cast<const float4*>(qrow) + 1);
        qa.x *= inv_sqrt_h; qa.y *= inv_sqrt_h; qa.z *= inv_sqrt_h; qa.w *= inv_sqrt_h;
        qb.x *= inv_sqrt_h; qb.y *= inv_sqrt_h; qb.z *= inv_sqrt_h; qb.w *= inv_sqrt_h;
        float er = g_expl * __half2float(__ldg(g_eh + (size_t)row * EDIM + hl));

        int j = beg;
        // main loop: 4 edges per iteration (2 per half), all valid
        for (; j + 4 <= end; j += 4) {
            int j0 = j + half;
            int j1 = j + 2 + half;
            int pk0 = __ldg(g_col_s + j0);
            int pk1 = __ldg(g_col_s + j1);
            int c0 = pk0 & 0xFFFFFF, c1 = pk1 & 0xFFFFFF;
            uint4 kr0 = __ldg(reinterpret_cast<const uint4*>(g_kh + (size_t)c0 * HDIM + hl * 8));
            uint4 kr1 = __ldg(reinterpret_cast<const uint4*>(g_kh + (size_t)c1 * HDIM + hl * 8));
            uint4 vr0 = __ldg(reinterpret_cast<const uint4*>(g_vh + (size_t)c0 * HDIM + hl * 8));
            uint4 vr1 = __ldg(reinterpret_cast<const uint4*>(g_vh + (size_t)c1 * HDIM + hl * 8));
            float ec0 = __half2float(__ldg(g_eh + (size_t)c0 * EDIM + hl));
            float ec1 = __half2float(__ldg(g_eh + (size_t)c1 * EDIM + hl));

            float z0 = dot8h(qa, qb, kr0) + er * ec0;
            float z1 = dot8h(qa, qb, kr1) + er * ec1;
            #pragma unroll
            for (int o = 8; o > 0; o >>= 1) {
                z0 += __shfl_xor_sync(0xffffffffu, z0, o);
                z1 += __shfl_xor_sync(0xffffffffu, z1, o);
            }
            float e00 = __expf(z0);
            float e01 = __expf(z1);
            float pw0 = s_pexp[((unsigned)pk0) >> 24];
            float pw1 = s_pexp[((unsigned)pk1) >> 24];
            d0 += e00 + e01;
            d1 += pw0 + pw1;

            float2 v0[4], v1[4];
            v0[0] = __half22float2(*reinterpret_cast<__half2*>(&vr0.x));
            v0[1] = __half22float2(*reinterpret_cast<__half2*>(&vr0.y));
            v0[2] = __half22float2(*reinterpret_cast<__half2*>(&vr0.z));
            v0[3] = __half22float2(*reinterpret_cast<__half2*>(&vr0.w));
            v1[0] = __half22float2(*reinterpret_cast<__half2*>(&vr1.x));
            v1[1] = __half22float2(*reinterpret_cast<__half2*>(&vr1.y));
            v1[2] = __half22float2(*reinterpret_cast<__half2*>(&vr1.z));
            v1[3] = __half22float2(*reinterpret_cast<__half2*>(&vr1.w));
            #pragma unroll
            for (int i = 0; i < 4; i++) {
                acc0[2*i]   += e00 * v0[i].x + e01 * v1[i].x;
                acc0[2*i+1] += e00 * v0[i].y + e01 * v1[i].y;
                acc1[2*i]   += pw0 * v0[i].x + pw1 * v1[i].x;
                acc1[2*i+1] += pw0 * v0[i].y + pw1 * v1[i].y;
            }
        }
        // tail: up to 3 edges, 2 per step with per-half predication
        for (; j < end; j += 2) {
            int jj = j + half;
            bool valid = jj < end;
            int pk0 = __ldg(g_col_s + (valid ? jj : beg));
            int c0 = pk0 & 0xFFFFFF;
            uint4 kr0 = __ldg(reinterpret_cast<const uint4*>(g_kh + (size_t)c0 * HDIM + hl * 8));
            uint4 vr0 = __ldg(reinterpret_cast<const uint4*>(g_vh + (size_t)c0 * HDIM + hl * 8));
            float ec0 = __half2float(__ldg(g_eh + (size_t)c0 * EDIM + hl));
            float z0 = dot8h(qa, qb, kr0) + er * ec0;
            #pragma unroll
            for (int o = 8; o > 0; o >>= 1)
                z0 += __shfl_xor_sync(0xffffffffu, z0, o);
            float e00 = valid ? __expf(z0) : 0.f;
            float pw0 = valid ? s_pexp[((unsigned)pk0) >> 24] : 0.f;
            d0 += e00;
            d1 += pw0;
            float2 v0[4];
            v0[0] = __half22float2(*reinterpret_cast<__half2*>(&vr0.x));
            v0[1] = __half22float2(*reinterpret_cast<__half2*>(&vr0.y));
            v0[2] = __half22float2(*reinterpret_cast<__half2*>(&vr0.z));
            v0[3] = __half22float2(*reinterpret_cast<__half2*>(&vr0.w));
            #pragma unroll
            for (int i = 0; i < 4; i++) {
                acc0[2*i]   += e00 * v0[i].x;
                acc0[2*i+1] += e00 * v0[i].y;
                acc1[2*i]   += pw0 * v0[i].x;
                acc1[2*i+1] += pw0 * v0[i].y;
            }
        }

        // combine halves
        d0 += __shfl_xor_sync(0xffffffffu, d0, 16);
        d1 += __shfl_xor_sync(0xffffffffu, d1, 16);
        float i0 = 0.5f / d0;
        float i1 = 0.5f / d1;
        #pragma unroll
        for (int i = 0; i < 8; i++) {
            acc0[i] += __shfl_xor_sync(0xffffffffu, acc0[i], 16);
            acc1[i] += __shfl_xor_sync(0xffffffffu, acc1[i], 16);
            res[i] = i0 * acc0[i] + i1 * acc1[i];
        }
    } else {
        #pragma unroll
        for (int i = 0; i < 8; i++) res[i] = 0.f;
    }

    if (half == 0) {
        float4* o = reinterpret_cast<float4*>(out + (size_t)row * HDIM + hl * 8);
        o[0] = make_float4(res[0], res[1], res[2], res[3]);
        o[1] = make_float4(res[4], res[5], res[6], res[7]);
    }
}

// ---------------------------------------------------------------------------
extern "C" void kernel_launch(void* const* d_in, const int* in_sizes, int n_in,
                              void* d_out, int out_size) {
    const float* q       = (const float*)d_in[0];
    const float* k       = (const float*)d_in[1];
    const float* v       = (const float*)d_in[2];
    const float* eigs    = (const float*)d_in[3];
    const float* lambda0 = (const float*)d_in[4];
    const float* path_w  = (const float*)d_in[5];
    const int*   indices = (const int*)d_in[6];
    const int*   ptype   = (const int*)d_in[7];
    float*       out     = (float*)d_out;

    int n_edges = in_sizes[6] / 2;
    int n_nodes = in_sizes[0] / HDIM;
    if (n_edges > EDGES)  n_edges = EDGES;
    if (n_nodes > NNODES) n_nodes = NNODES;

    int eb8 = (n_edges / 8 + 255) / 256 + 1;
    int rb  = (n_nodes * 32 + 255) / 256;

    k_prep_hist<<<2048, 256>>>(k, v, eigs, lambda0, path_w, indices,
                               n_nodes, n_edges);
    k_scan<<<1, 1024>>>(n_nodes);
    k_scatter<<<eb8, 256>>>(indices, ptype, n_edges);
    k_fused<<<rb, 256>>>(q, out, n_nodes);
}

// round 8
// speedup vs baseline: 1.0702x; 1.0702x over previous
#include <cuda_runtime.h>
#include <cuda_fp16.h>
#include <math.h>

#define NNODES 100000
#define EDGES  3200000
#define HDIM   128
#define EDIM   16
#define PTYPES 6
#define ECACHE 128   // per-warp smem cache entries (degree beyond -> global spill)

// ---- __device__ scratch (allocations are banned) ----
__device__ int    g_cnt[NNODES];
__device__ int    g_rowptr[NNODES + 1];
__device__ int    g_rowpos[NNODES];
__device__ int    g_col_s[EDGES];       // CSR-ordered packed (col | ptype<<24)
__device__ float  g_e0[EDGES];          // overflow spill for e0 (rarely touched)
__device__ __half g_kh[NNODES * HDIM];  // fp16 k     (25.6 MB)
__device__ __half g_vh[NNODES * HDIM];  // fp16 v     (25.6 MB)
__device__ __half g_eh[NNODES * EDIM];  // fp16 eigs   (3.2 MB)
__device__ float  g_pexp[PTYPES];
__device__ float  g_expl;

// ---------------------------------------------------------------------------
// 0) prep: zero histogram, exp tables, fp16 copies of k, v, eigs
// ---------------------------------------------------------------------------
__global__ void k_prep(const float* __restrict__ k,
                       const float* __restrict__ v,
                       const float* __restrict__ eigs,
                       const float* __restrict__ lambda0,
                       const float* __restrict__ path_w, int n_nodes) {
    int tid = blockIdx.x * blockDim.x + threadIdx.x;
    int stride = gridDim.x * blockDim.x;

    for (int i = tid; i < n_nodes; i += stride) g_cnt[i] = 0;

    int nk4 = n_nodes * (HDIM / 4);
    for (int i = tid; i < nk4; i += stride) {
        float4 f = __ldg(reinterpret_cast<const float4*>(k) + i);
        __half2 lo = __floats2half2_rn(f.x, f.y);
        __half2 hi = __floats2half2_rn(f.z, f.w);
        uint2 o;
        o.x = *reinterpret_cast<unsigned*>(&lo);
        o.y = *reinterpret_cast<unsigned*>(&hi);
        reinterpret_cast<uint2*>(g_kh)[i] = o;
    }
    for (int i = tid; i < nk4; i += stride) {
        float4 f = __ldg(reinterpret_cast<const float4*>(v) + i);
        __half2 lo = __floats2half2_rn(f.x, f.y);
        __half2 hi = __floats2half2_rn(f.z, f.w);
        uint2 o;
        o.x = *reinterpret_cast<unsigned*>(&lo);
        o.y = *reinterpret_cast<unsigned*>(&hi);
        reinterpret_cast<uint2*>(g_vh)[i] = o;
    }
    int ne4 = n_nodes * (EDIM / 4);
    for (int i = tid; i < ne4; i += stride) {
        float4 f = __ldg(reinterpret_cast<const float4*>(eigs) + i);
        __half2 lo = __floats2half2_rn(f.x, f.y);
        __half2 hi = __floats2half2_rn(f.z, f.w);
        uint2 o;
        o.x = *reinterpret_cast<unsigned*>(&lo);
        o.y = *reinterpret_cast<unsigned*>(&hi);
        reinterpret_cast<uint2*>(g_eh)[i] = o;
    }

    if (tid < PTYPES) g_pexp[tid] = expf(path_w[tid]);
    if (tid == 0)     g_expl = expf(lambda0[0]);
}

// ---------------------------------------------------------------------------
// 1) histogram of destination rows — 8 edges/thread, vectorized
// ---------------------------------------------------------------------------
__global__ void k_hist(const int* __restrict__ indices, int n_edges) {
    int t = blockIdx.x * blockDim.x + threadIdx.x;
    int base = t * 8;
    if (base + 8 <= n_edges) {
        int4 a = __ldg(reinterpret_cast<const int4*>(indices) + t * 2);
        int4 b = __ldg(reinterpret_cast<const int4*>(indices) + t * 2 + 1);
        atomicAdd(&g_cnt[a.x], 1); atomicAdd(&g_cnt[a.y], 1);
        atomicAdd(&g_cnt[a.z], 1); atomicAdd(&g_cnt[a.w], 1);
        atomicAdd(&g_cnt[b.x], 1); atomicAdd(&g_cnt[b.y], 1);
        atomicAdd(&g_cnt[b.z], 1); atomicAdd(&g_cnt[b.w], 1);
    } else {
        for (int e = base; e < n_edges; e++)
            atomicAdd(&g_cnt[__ldg(indices + e)], 1);
    }
}

// ---------------------------------------------------------------------------
// 2) exclusive scan (single block)
// ---------------------------------------------------------------------------
__global__ void k_scan(int n) {
    __shared__ int part[1024];
    int tid = threadIdx.x;
    int chunk = (n + 1023) / 1024;
    int start = tid * chunk;
    int end   = min(start + chunk, n);
    int s = 0;
    for (int i = start; i < end; i++) s += g_cnt[i];
    part[tid] = s;
    __syncthreads();
    for (int off = 1; off < 1024; off <<= 1) {
        int v = 0;
        if (tid >= off) v = part[tid - off];
        __syncthreads();
        if (tid >= off) part[tid] += v;
        __syncthreads();
    }
    int run = (tid == 0) ? 0 : part[tid - 1];
    for (int i = start; i < end; i++) {
        g_rowptr[i] = run;
        g_rowpos[i] = run;
        run += g_cnt[i];
    }
    if (end == n && start <= n) g_rowptr[n] = run;
}

// ---------------------------------------------------------------------------
// 3) scatter — 8 edges/thread, single packed 4B write per edge
// ---------------------------------------------------------------------------
__global__ void k_scatter(const int* __restrict__ indices,
                          const int* __restrict__ ptype, int n_edges) {
    int t = blockIdx.x * blockDim.x + threadIdx.x;
    int base = t * 8;
    if (base + 8 <= n_edges) {
        int4 r0 = __ldg(reinterpret_cast<const int4*>(indices) + t * 2);
        int4 r1 = __ldg(reinterpret_cast<const int4*>(indices) + t * 2 + 1);
        int4 c0 = __ldg(reinterpret_cast<const int4*>(indices + n_edges) + t * 2);
        int4 c1 = __ldg(reinterpret_cast<const int4*>(indices + n_edges) + t * 2 + 1);
        int4 p0 = __ldg(reinterpret_cast<const int4*>(ptype) + t * 2);
        int4 p1 = __ldg(reinterpret_cast<const int4*>(ptype) + t * 2 + 1);
        int pos;
        pos = atomicAdd(&g_rowpos[r0.x], 1); g_col_s[pos] = c0.x | (p0.x << 24);
        pos = atomicAdd(&g_rowpos[r0.y], 1); g_col_s[pos] = c0.y | (p0.y << 24);
        pos = atomicAdd(&g_rowpos[r0.z], 1); g_col_s[pos] = c0.z | (p0.z << 24);
        pos = atomicAdd(&g_rowpos[r0.w], 1); g_col_s[pos] = c0.w | (p0.w << 24);
        pos = atomicAdd(&g_rowpos[r1.x], 1); g_col_s[pos] = c1.x | (p1.x << 24);
        pos = atomicAdd(&g_rowpos[r1.y], 1); g_col_s[pos] = c1.y | (p1.y << 24);
        pos = atomicAdd(&g_rowpos[r1.z], 1); g_col_s[pos] = c1.z | (p1.z << 24);
        pos = atomicAdd(&g_rowpos[r1.w], 1); g_col_s[pos] = c1.w | (p1.w << 24);
    } else {
        for (int e = base; e < n_edges; e++) {
            int row = __ldg(indices + e);
            int col = __ldg(indices + n_edges + e);
            int pt  = __ldg(ptype + e);
            int pos = atomicAdd(&g_rowpos[row], 1);
            g_col_s[pos] = col | (pt << 24);
        }
    }
}

// ---------------------------------------------------------------------------
// 4) fused: warp per row, half-warp per edge, TWO sweeps.
//    Sweep 1: k/eig gather -> e0 -> smem cache (pk, e0); d0, d1.
//    Sweep 2: v gather with final scalar weight -> single accumulator set.
// ---------------------------------------------------------------------------
__device__ __forceinline__ float dot8h(float4 qa, float4 qb, uint4 kr) {
    float2 k0 = __half22float2(*reinterpret_cast<__half2*>(&kr.x));
    float2 k1 = __half22float2(*reinterpret_cast<__half2*>(&kr.y));
    float2 k2 = __half22float2(*reinterpret_cast<__half2*>(&kr.z));
    float2 k3 = __half22float2(*reinterpret_cast<__half2*>(&kr.w));
    return qa.x * k0.x + qa.y * k0.y + qa.z * k1.x + qa.w * k1.y
         + qb.x * k2.x + qb.y * k2.y + qb.z * k3.x + qb.w * k3.y;
}

__global__ void __launch_bounds__(256)
k_fused(const float* __restrict__ q, float* __restrict__ out, int n_nodes) {
    __shared__ float s_pexp[PTYPES];
    __shared__ int   s_pk[8][ECACHE];
    __shared__ float s_e0[8][ECACHE];
    if (threadIdx.x < PTYPES) s_pexp[threadIdx.x] = g_pexp[threadIdx.x];
    __syncthreads();

    int warp = (blockIdx.x * blockDim.x + threadIdx.x) >> 5;
    int lane = threadIdx.x & 31;
    const int wlb = (threadIdx.x >> 5) & 7;
    if (warp >= n_nodes) return;
    const int row  = warp;
    const int half = lane >> 4;
    const int hl   = lane & 15;
    const int beg = g_rowptr[row];
    const int end = g_rowptr[row + 1];

    float res[8];
    if (beg < end) {
        const float inv_sqrt_h = 0.08838834764831845f;
        const float* qrow = q + (size_t)row * HDIM + hl * 8;
        float4 qa = __ldg(reinterpret_cast<const float4*>(qrow));
        float4 qb = __ldg(reinterpret_cast<const float4*>(qrow) + 1);
        qa.x *= inv_sqrt_h; qa.y *= inv_sqrt_h; qa.z *= inv_sqrt_h; qa.w *= inv_sqrt_h;
        qb.x *= inv_sqrt_h; qb.y *= inv_sqrt_h; qb.z *= inv_sqrt_h; qb.w *= inv_sqrt_h;
        float er = g_expl * __half2float(__ldg(g_eh + (size_t)row * EDIM + hl));

        // ---------------- sweep 1: scores ----------------
        float d0 = 0.f, d1 = 0.f;
        int j = beg;
        for (; j + 4 <= end; j += 4) {
            int j0 = j + half, j1 = j + 2 + half;
            int pk0 = __ldg(g_col_s + j0);
            int pk1 = __ldg(g_col_s + j1);
            int c0 = pk0 & 0xFFFFFF, c1 = pk1 & 0xFFFFFF;
            uint4 kr0 = __ldg(reinterpret_cast<const uint4*>(g_kh + (size_t)c0 * HDIM + hl * 8));
            uint4 kr1 = __ldg(reinterpret_cast<const uint4*>(g_kh + (size_t)c1 * HDIM + hl * 8));
            float ec0 = __half2float(__ldg(g_eh + (size_t)c0 * EDIM + hl));
            float ec1 = __half2float(__ldg(g_eh + (size_t)c1 * EDIM + hl));
            float z0 = dot8h(qa, qb, kr0) + er * ec0;
            float z1 = dot8h(qa, qb, kr1) + er * ec1;
            #pragma unroll
            for (int o = 8; o > 0; o >>= 1) {
                z0 += __shfl_xor_sync(0xffffffffu, z0, o);
                z1 += __shfl_xor_sync(0xffffffffu, z1, o);
            }
            float e00 = __expf(z0);
            float e01 = __expf(z1);
            d0 += e00 + e01;
            d1 += s_pexp[((unsigned)pk0) >> 24] + s_pexp[((unsigned)pk1) >> 24];
            if (hl == 0) {
                int x0 = j0 - beg, x1 = j1 - beg;
                if (x0 < ECACHE) { s_pk[wlb][x0] = pk0; s_e0[wlb][x0] = e00; }
                else             g_e0[j0] = e00;
                if (x1 < ECACHE) { s_pk[wlb][x1] = pk1; s_e0[wlb][x1] = e01; }
                else             g_e0[j1] = e01;
            }
        }
        for (; j < end; j += 2) {
            int jj = j + half;
            bool valid = jj < end;
            int pk0 = __ldg(g_col_s + (valid ? jj : beg));
            int c0 = pk0 & 0xFFFFFF;
            uint4 kr0 = __ldg(reinterpret_cast<const uint4*>(g_kh + (size_t)c0 * HDIM + hl * 8));
            float ec0 = __half2float(__ldg(g_eh + (size_t)c0 * EDIM + hl));
            float z0 = dot8h(qa, qb, kr0) + er * ec0;
            #pragma unroll
            for (int o = 8; o > 0; o >>= 1)
                z0 += __shfl_xor_sync(0xffffffffu, z0, o);
            float e00 = valid ? __expf(z0) : 0.f;
            d0 += e00;
            d1 += valid ? s_pexp[((unsigned)pk0) >> 24] : 0.f;
            if (hl == 0 && valid) {
                int x0 = jj - beg;
                if (x0 < ECACHE) { s_pk[wlb][x0] = pk0; s_e0[wlb][x0] = e00; }
                else             g_e0[jj] = e00;
            }
        }
        d0 += __shfl_xor_sync(0xffffffffu, d0, 16);
        d1 += __shfl_xor_sync(0xffffffffu, d1, 16);
        __syncwarp();

        // ---------------- sweep 2: weighted v gather ----------------
        const float i0 = 0.5f / d0;
        const float i1 = 0.5f / d1;
        float acc[8] = {0,0,0,0,0,0,0,0};
        j = beg;
        for (; j + 4 <= end; j += 4) {
            int j0 = j + half, j1 = j + 2 + half;
            int x0 = j0 - beg, x1 = j1 - beg;
            int pk0, pk1; float e00, e01;
            if (x0 < ECACHE) { pk0 = s_pk[wlb][x0]; e00 = s_e0[wlb][x0]; }
            else             { pk0 = __ldg(g_col_s + j0); e00 = g_e0[j0]; }
            if (x1 < ECACHE) { pk1 = s_pk[wlb][x1]; e01 = s_e0[wlb][x1]; }
            else             { pk1 = __ldg(g_col_s + j1); e01 = g_e0[j1]; }
            int c0 = pk0 & 0xFFFFFF, c1 = pk1 & 0xFFFFFF;
            uint4 vr0 = __ldg(reinterpret_cast<const uint4*>(g_vh + (size_t)c0 * HDIM + hl * 8));
            uint4 vr1 = __ldg(reinterpret_cast<const uint4*>(g_vh + (size_t)c1 * HDIM + hl * 8));
            float w0 = e00 * i0 + s_pexp[((unsigned)pk0) >> 24] * i1;
            float w1 = e01 * i0 + s_pexp[((unsigned)pk1) >> 24] * i1;
            float2 v0[4], v1[4];
            v0[0] = __half22float2(*reinterpret_cast<__half2*>(&vr0.x));
            v0[1] = __half22float2(*reinterpret_cast<__half2*>(&vr0.y));
            v0[2] = __half22float2(*reinterpret_cast<__half2*>(&vr0.z));
            v0[3] = __half22float2(*reinterpret_cast<__half2*>(&vr0.w));
            v1[0] = __half22float2(*reinterpret_cast<__half2*>(&vr1.x));
            v1[1] = __half22float2(*reinterpret_cast<__half2*>(&vr1.y));
            v1[2] = __half22float2(*reinterpret_cast<__half2*>(&vr1.w ? vr1.w : vr1.w));
            v1[2] = __half22float2(*reinterpret_cast<__half2*>(&vr1.z));
            v1[3] = __half22float2(*reinterpret_cast<__half2*>(&vr1.w));
            #pragma unroll
            for (int i = 0; i < 4; i++) {
                acc[2*i]   += w0 * v0[i].x + w1 * v1[i].x;
                acc[2*i+1] += w0 * v0[i].y + w1 * v1[i].y;
            }
        }
        for (; j < end; j += 2) {
            int jj = j + half;
            bool valid = jj < end;
            int xs = valid ? (jj - beg) : 0;
            int pk0; float e00;
            if (xs < ECACHE) { pk0 = s_pk[wlb][xs]; e00 = s_e0[wlb][xs]; }
            else             { pk0 = __ldg(g_col_s + jj); e00 = g_e0[jj]; }
            int c0 = pk0 & 0xFFFFFF;
            uint4 vr0 = __ldg(reinterpret_cast<const uint4*>(g_vh + (size_t)c0 * HDIM + hl * 8));
            float w0 = valid ? (e00 * i0 + s_pexp[((unsigned)pk0) >> 24] * i1) : 0.f;
            float2 v0[4];
            v0[0] = __half22float2(*reinterpret_cast<__half2*>(&vr0.x));
            v0[1] = __half22float2(*reinterpret_cast<__half2*>(&vr0.y));
            v0[2] = __half22float2(*reinterpret_cast<__half2*>(&vr0.z));
            v0[3] = __half22float2(*reinterpret_cast<__half2*>(&vr0.w));
            #pragma unroll
            for (int i = 0; i < 4; i++) {
                acc[2*i]   += w0 * v0[i].x;
                acc[2*i+1] += w0 * v0[i].y;
            }
        }
        #pragma unroll
        for (int i = 0; i < 8; i++) {
            acc[i] += __shfl_xor_sync(0xffffffffu, acc[i], 16);
            res[i] = acc[i];
        }
    } else {
        #pragma unroll
        for (int i = 0; i < 8; i++) res[i] = 0.f;
    }

    if (half == 0) {
        float4* o = reinterpret_cast<float4*>(out + (size_t)row * HDIM + hl * 8);
        o[0] = make_float4(res[0], res[1], res[2], res[3]);
        o[1] = make_float4(res[4], res[5], res[6], res[7]);
    }
}

// ---------------------------------------------------------------------------
extern "C" void kernel_launch(void* const* d_in, const int* in_sizes, int n_in,
                              void* d_out, int out_size) {
    const float* q       = (const float*)d_in[0];
    const float* k       = (const float*)d_in[1];
    const float* v       = (const float*)d_in[2];
    const float* eigs    = (const float*)d_in[3];
    const float* lambda0 = (const float*)d_in[4];
    const float* path_w  = (const float*)d_in[5];
    const int*   indices = (const int*)d_in[6];
    const int*   ptype   = (const int*)d_in[7];
    float*       out     = (float*)d_out;

    int n_edges = in_sizes[6] / 2;
    int n_nodes = in_sizes[0] / HDIM;
    if (n_edges > EDGES)  n_edges = EDGES;
    if (n_nodes > NNODES) n_nodes = NNODES;

    int eb8 = (n_edges / 8 + 255) / 256 + 1;
    int rb  = (n_nodes * 32 + 255) / 256;

    k_prep<<<2048, 256>>>(k, v, eigs, lambda0, path_w, n_nodes);
    k_hist<<<eb8, 256>>>(indices, n_edges);
    k_scan<<<1, 1024>>>(n_nodes);
    k_scatter<<<eb8, 256>>>(indices, ptype, n_edges);
    k_fused<<<rb, 256>>>(q, out, n_nodes);
}